// round 12
// baseline (speedup 1.0000x reference)
#include <cuda_runtime.h>
#include <cstdint>

// out(b, y, x) = bilinear sample of img_b at (y + 5 + py, x + 5 + px), zero
// outside [0, 522).
// FOUR output rows x EIGHT consecutive px per thread. Source rows Y..Y+4;
// per row the span [c, c+8] (9 floats) is covered by 3 aligned float4 loads.
// Per thread: 15 LDG.128 + 4 STG.128 serve 32 px (7.5 B loaded / px).
// Column offset/weight hoisted (validated R6, rel_err ~1.2e-5). Row
// alignment: 522 % 4 == 2 -> source rows alternate shift M0 / (M0+2)&3;
// one uniform 4-way template dispatch, zero per-pixel integer work.
// Each row's quads are reduced to horizontal lerps immediately so only one
// row of quads is live at a time (register control).
// Buffer-end check (worst fast case Y=517, X0=9, last thread c+8 =
// 521*522 + 9 + 504 + 8 = 272483 = last element; third quad ends at
// ((c+8)&~3)+3 <= 272483): no overrun.

static constexpr int NPAD = 522;
static constexpr int NOUT = 512;
static constexpr int B    = 256;

__device__ __forceinline__ float comp3(const float4& A, const float4& Bq,
                                       const float4& C, int i) {
    switch (i) {
    case 0:  return A.x;  case 1:  return A.y;  case 2:  return A.z;  case 3:  return A.w;
    case 4:  return Bq.x; case 5:  return Bq.y; case 6:  return Bq.z; case 7:  return Bq.w;
    case 8:  return C.x;  case 9:  return C.y;  case 10: return C.z;  default: return C.w;
    }
}

template <int M0>
__device__ __forceinline__ void fast_oct(
    const float* __restrict__ base, float* __restrict__ o0,
    int tid, int Y, int X0, float wx, const float* __restrict__ wy)
{
    const int c0 = Y * NPAD + X0 + 8 * tid;

    // Horizontal lerps per source row; quads freed immediately after use.
    float t[5][8];
    #pragma unroll
    for (int r = 0; r < 5; r++) {
        const int c = c0 + r * NPAD;
        const float4* q = reinterpret_cast<const float4*>(base + (c & ~3));
        const float4 A  = __ldg(q);
        const float4 Bq = __ldg(q + 1);
        const float4 C  = __ldg(q + 2);
        const int M = (r & 1) ? ((M0 + 2) & 3) : M0;
        #pragma unroll
        for (int i = 0; i < 8; i++) {
            const float a  = comp3(A, Bq, C, M + i);
            const float bb = comp3(A, Bq, C, M + i + 1);
            t[r][i] = a + wx * (bb - a);
        }
    }

    // Vertical lerps + stores (two float4 per output row).
    #pragma unroll
    for (int r = 0; r < 4; r++) {
        float4 v0, v1;
        v0.x = t[r][0] + wy[r] * (t[r + 1][0] - t[r][0]);
        v0.y = t[r][1] + wy[r] * (t[r + 1][1] - t[r][1]);
        v0.z = t[r][2] + wy[r] * (t[r + 1][2] - t[r][2]);
        v0.w = t[r][3] + wy[r] * (t[r + 1][3] - t[r][3]);
        v1.x = t[r][4] + wy[r] * (t[r + 1][4] - t[r][4]);
        v1.y = t[r][5] + wy[r] * (t[r + 1][5] - t[r][5]);
        v1.z = t[r][6] + wy[r] * (t[r + 1][6] - t[r][6]);
        v1.w = t[r][7] + wy[r] * (t[r + 1][7] - t[r][7]);
        float4* op = reinterpret_cast<float4*>(o0 + (size_t)r * NOUT + 8 * tid);
        op[0] = v0;
        op[1] = v1;
    }
}

__global__ __launch_bounds__(64) void extract_patches_kernel(
    const float* __restrict__ img,   // (B, 522, 522, 1)
    const float* __restrict__ pos,   // (B, 2)  [px, py]
    float* __restrict__ out)         // (B, 512, 512, 1)
{
    const int b   = blockIdx.z;
    const int y0  = blockIdx.y * 4;
    const int tid = threadIdx.x;

    const float px = __ldg(pos + 2 * b);
    const float py = __ldg(pos + 2 * b + 1);

    // Exact reference row arithmetic for all 4 output rows.
    float wy[4];
    int   Yr[4];
    #pragma unroll
    for (int r = 0; r < 4; r++) {
        const float sy = (float)(y0 + r + 5) + py;
        const float yf = floorf(sy);
        wy[r] = sy - yf;
        Yr[r] = (int)yf;
    }
    const int Y = Yr[0];

    const float s0  = 5.0f + px;
    const float x0f = floorf(s0);
    const float wx  = s0 - x0f;
    const int   X0  = (int)x0f;

    const float* base = img + (size_t)b * (NPAD * NPAD);
    float* o0 = out + ((size_t)b * NOUT + y0) * NOUT;

    const bool fast = (X0 >= 0) & (X0 <= 9) & (Y >= 0) & (Y <= NPAD - 5) &
                      (Yr[1] == Y + 1) & (Yr[2] == Y + 2) & (Yr[3] == Y + 3);

    if (fast) {
        const int m = (2 * Y + X0) & 3;   // uniform across block (8*tid % 4 == 0)
        switch (m) {
        case 0:  fast_oct<0>(base, o0, tid, Y, X0, wx, wy); break;
        case 1:  fast_oct<1>(base, o0, tid, Y, X0, wx, wy); break;
        case 2:  fast_oct<2>(base, o0, tid, Y, X0, wx, wy); break;
        default: fast_oct<3>(base, o0, tid, Y, X0, wx, wy); break;
        }
    } else {
        // Exact per-pixel path with full predication (handles zero fill).
        #pragma unroll
        for (int r = 0; r < 4; r++) {
            const int   yy   = y0 + r;
            const float sy   = (float)(yy + 5) + py;
            const float yf   = floorf(sy);
            const float wyp  = sy - yf;
            const int   Yi   = (int)yf;
            const bool vy0 = ((unsigned)Yi       < (unsigned)NPAD);
            const bool vy1 = ((unsigned)(Yi + 1) < (unsigned)NPAD);
            const float* rr = base + (ptrdiff_t)Yi * NPAD;
            float* orow = out + ((size_t)b * NOUT + yy) * NOUT;
            #pragma unroll
            for (int i = 0; i < 8; i++) {
                const int   x    = 8 * tid + i;
                const float sx   = (float)(x + 5) + px;
                const float xf   = floorf(sx);
                const float wxp  = sx - xf;
                const int   X    = (int)xf;
                const bool vx0 = ((unsigned)X       < (unsigned)NPAD);
                const bool vx1 = ((unsigned)(X + 1) < (unsigned)NPAD);
                const float* p0 = rr + X;
                float g00 = 0.0f, g01 = 0.0f, g10 = 0.0f, g11 = 0.0f;
                if (vy0 && vx0) g00 = __ldg(p0);
                if (vy0 && vx1) g01 = __ldg(p0 + 1);
                if (vy1 && vx0) g10 = __ldg(p0 + NPAD);
                if (vy1 && vx1) g11 = __ldg(p0 + NPAD + 1);
                const float top = g00 + wxp * (g01 - g00);
                const float bot = g10 + wxp * (g11 - g10);
                orow[x] = top + wyp * (bot - top);
            }
        }
    }
}

extern "C" void kernel_launch(void* const* d_in, const int* in_sizes, int n_in,
                              void* d_out, int out_size)
{
    const float* img = (const float*)d_in[0];   // padded_obj: 256*522*522*1 f32
    const float* pos = (const float*)d_in[1];   // positions:  256*2 f32
    float* out = (float*)d_out;                 // 256*512*512*1 f32

    dim3 block(64, 1, 1);                       // 64 thr x 8 px = 512 px/row
    dim3 grid(1, NOUT / 4, B);                  // (1, 128, 256)
    extract_patches_kernel<<<grid, block>>>(img, pos, out);
}

// round 13
// speedup vs baseline: 1.1204x; 1.1204x over previous
#include <cuda_runtime.h>
#include <cstdint>

// out(b, y, x) = bilinear sample of img_b at (y + 5 + py, x + 5 + px), zero
// outside [0, 522).
// 256-thread CTA = two 128-thread groups; each group produces 4 output rows
// x 512 px (4 consecutive px per thread, float4 everywhere). Per thread:
// 10 LDG.128 (front-batched, MLP=10, dense 16 B lane stride) + 4 STG.128.
// Column offset/weight hoisted (validated R6: rel_err ~1.2e-5). Row
// alignment: 522 % 4 == 2 -> source rows alternate shift M0 / (M0+2)&3, and
// group row-offset 4g preserves m = (2Y+X0)&3, so ONE uniform 4-way template
// dispatch covers the whole CTA. Worst-case aligned-quad read ends exactly
// at the buffer's last element (521*522+9+508 -> 272483): no overrun.

static constexpr int NPAD = 522;
static constexpr int NOUT = 512;
static constexpr int B    = 256;

__device__ __forceinline__ float comp(const float4& A, const float4& Bq, int i) {
    switch (i) {
    case 0: return A.x;  case 1: return A.y;  case 2: return A.z;  case 3: return A.w;
    case 4: return Bq.x; case 5: return Bq.y; case 6: return Bq.z; default: return Bq.w;
    }
}

template <int M0>
__device__ __forceinline__ void fast_quad(
    const float* __restrict__ base, float* __restrict__ o0,
    int lane, int Y, int X0, float wx, const float* __restrict__ wy)
{
    const int c0 = Y * NPAD + X0 + 4 * lane;

    // 5 source rows, 2 aligned quads each. All loads issued up front.
    float4 A[5], Bq[5];
    #pragma unroll
    for (int r = 0; r < 5; r++) {
        const int c = c0 + r * NPAD;
        const float4* q = reinterpret_cast<const float4*>(base + (c & ~3));
        A[r]  = __ldg(q);
        Bq[r] = __ldg(q + 1);
    }

    // Horizontal lerps: shift M0 for even source rows, (M0+2)&3 for odd.
    float t[5][4];
    #pragma unroll
    for (int r = 0; r < 5; r++) {
        const int M = (r & 1) ? ((M0 + 2) & 3) : M0;
        #pragma unroll
        for (int i = 0; i < 4; i++) {
            const float a  = comp(A[r], Bq[r], M + i);
            const float bb = comp(A[r], Bq[r], M + i + 1);
            t[r][i] = a + wx * (bb - a);
        }
    }

    // Vertical lerps + stores.
    #pragma unroll
    for (int r = 0; r < 4; r++) {
        float4 v;
        v.x = t[r][0] + wy[r] * (t[r + 1][0] - t[r][0]);
        v.y = t[r][1] + wy[r] * (t[r + 1][1] - t[r][1]);
        v.z = t[r][2] + wy[r] * (t[r + 1][2] - t[r][2]);
        v.w = t[r][3] + wy[r] * (t[r + 1][3] - t[r][3]);
        *reinterpret_cast<float4*>(o0 + (size_t)r * NOUT + 4 * lane) = v;
    }
}

__global__ __launch_bounds__(256) void extract_patches_kernel(
    const float* __restrict__ img,   // (B, 522, 522, 1)
    const float* __restrict__ pos,   // (B, 2)  [px, py]
    float* __restrict__ out)         // (B, 512, 512, 1)
{
    const int b    = blockIdx.z;
    const int g    = threadIdx.x >> 7;          // group 0/1 within CTA
    const int lane = threadIdx.x & 127;
    const int y0   = blockIdx.y * 8 + g * 4;    // first of this group's 4 rows

    const float px = __ldg(pos + 2 * b);
    const float py = __ldg(pos + 2 * b + 1);

    // Exact reference row arithmetic for this group's 4 output rows.
    float wy[4];
    int   Yr[4];
    #pragma unroll
    for (int r = 0; r < 4; r++) {
        const float sy = (float)(y0 + r + 5) + py;
        const float yf = floorf(sy);
        wy[r] = sy - yf;
        Yr[r] = (int)yf;
    }
    const int Y = Yr[0];

    const float s0  = 5.0f + px;
    const float x0f = floorf(s0);
    const float wx  = s0 - x0f;
    const int   X0  = (int)x0f;

    const float* base = img + (size_t)b * (NPAD * NPAD);
    float* o0 = out + ((size_t)b * NOUT + y0) * NOUT;

    const bool fast = (X0 >= 0) & (X0 <= 9) & (Y >= 0) & (Y <= NPAD - 5) &
                      (Yr[1] == Y + 1) & (Yr[2] == Y + 2) & (Yr[3] == Y + 3);

    if (fast) {
        // m is identical for both groups: 2*(Y+4g)+X0 == 2*Y+X0 (mod 4).
        const int m = (2 * Y + X0) & 3;
        switch (m) {
        case 0:  fast_quad<0>(base, o0, lane, Y, X0, wx, wy); break;
        case 1:  fast_quad<1>(base, o0, lane, Y, X0, wx, wy); break;
        case 2:  fast_quad<2>(base, o0, lane, Y, X0, wx, wy); break;
        default: fast_quad<3>(base, o0, lane, Y, X0, wx, wy); break;
        }
    } else {
        // Exact per-pixel path with full predication (handles zero fill).
        #pragma unroll
        for (int r = 0; r < 4; r++) {
            const int   yy   = y0 + r;
            const float sy   = (float)(yy + 5) + py;
            const float yf   = floorf(sy);
            const float wyp  = sy - yf;
            const int   Yi   = (int)yf;
            const bool vy0 = ((unsigned)Yi       < (unsigned)NPAD);
            const bool vy1 = ((unsigned)(Yi + 1) < (unsigned)NPAD);
            const float* rr = base + (ptrdiff_t)Yi * NPAD;
            float* orow = out + ((size_t)b * NOUT + yy) * NOUT;
            #pragma unroll
            for (int i = 0; i < 4; i++) {
                const int   x    = 4 * lane + i;
                const float sx   = (float)(x + 5) + px;
                const float xf   = floorf(sx);
                const float wxp  = sx - xf;
                const int   X    = (int)xf;
                const bool vx0 = ((unsigned)X       < (unsigned)NPAD);
                const bool vx1 = ((unsigned)(X + 1) < (unsigned)NPAD);
                const float* p0 = rr + X;
                float g00 = 0.0f, g01 = 0.0f, g10 = 0.0f, g11 = 0.0f;
                if (vy0 && vx0) g00 = __ldg(p0);
                if (vy0 && vx1) g01 = __ldg(p0 + 1);
                if (vy1 && vx0) g10 = __ldg(p0 + NPAD);
                if (vy1 && vx1) g11 = __ldg(p0 + NPAD + 1);
                const float top = g00 + wxp * (g01 - g00);
                const float bot = g10 + wxp * (g11 - g10);
                orow[x] = top + wyp * (bot - top);
            }
        }
    }
}

extern "C" void kernel_launch(void* const* d_in, const int* in_sizes, int n_in,
                              void* d_out, int out_size)
{
    const float* img = (const float*)d_in[0];   // padded_obj: 256*522*522*1 f32
    const float* pos = (const float*)d_in[1];   // positions:  256*2 f32
    float* out = (float*)d_out;                 // 256*512*512*1 f32

    dim3 block(256, 1, 1);
    dim3 grid(1, NOUT / 8, B);                  // (1, 64, 256)
    extract_patches_kernel<<<grid, block>>>(img, pos, out);
}